// round 14
// baseline (speedup 1.0000x reference)
#include <cuda_runtime.h>
#include <cuda_fp16.h>
#include <math.h>

#define BB   8
#define SS   1024
#define DD   768
#define HH   12
#define DHD  64
#define BHN  (BB*HH)

#define LOG2E 1.4426950408889634f

// fp16 scratch
__device__ __half g_Xh[BB * SS * DD];          // X, fp16
__device__ __half g_Wh[3 * DD * DD];           // Wq|Wk|Wv, fp16
__device__ __half g_Q [BHN * SS * DHD];        // s-major [bh][s][d]
__device__ __half g_K [BHN * SS * DHD];        // K rows pre-scaled by 0.125*log2e*click
__device__ __half g_V [BHN * SS * DHD];

// ---------------------------------------------------------------------------
// helpers
// ---------------------------------------------------------------------------
__device__ __forceinline__ void mma16(float c[4], const unsigned a[4],
                                      unsigned b0, unsigned b1) {
    asm volatile(
        "mma.sync.aligned.m16n8k16.row.col.f32.f16.f16.f32 "
        "{%0,%1,%2,%3}, {%4,%5,%6,%7}, {%8,%9}, {%0,%1,%2,%3};"
        : "+f"(c[0]), "+f"(c[1]), "+f"(c[2]), "+f"(c[3])
        : "r"(a[0]), "r"(a[1]), "r"(a[2]), "r"(a[3]), "r"(b0), "r"(b1));
}
// fp16 accumulator variant: D/C = 2 packed half2 regs,
// reg0 = (row g, cols 2tg,2tg+1), reg1 = (row g+8, same cols).
__device__ __forceinline__ void mma16h(unsigned c[2], const unsigned a[4],
                                       unsigned b0, unsigned b1) {
    asm volatile(
        "mma.sync.aligned.m16n8k16.row.col.f16.f16.f16.f16 "
        "{%0,%1}, {%2,%3,%4,%5}, {%6,%7}, {%0,%1};"
        : "+r"(c[0]), "+r"(c[1])
        : "r"(a[0]), "r"(a[1]), "r"(a[2]), "r"(a[3]), "r"(b0), "r"(b1));
}
__device__ __forceinline__ void ldsm4(unsigned r[4], const void* p) {
    unsigned a = (unsigned)__cvta_generic_to_shared(p);
    asm volatile("ldmatrix.sync.aligned.m8n8.x4.shared.b16 {%0,%1,%2,%3}, [%4];"
                 : "=r"(r[0]), "=r"(r[1]), "=r"(r[2]), "=r"(r[3]) : "r"(a));
}
__device__ __forceinline__ void ldsm4t(unsigned r[4], const void* p) {
    unsigned a = (unsigned)__cvta_generic_to_shared(p);
    asm volatile("ldmatrix.sync.aligned.m8n8.x4.trans.shared.b16 {%0,%1,%2,%3}, [%4];"
                 : "=r"(r[0]), "=r"(r[1]), "=r"(r[2]), "=r"(r[3]) : "r"(a));
}
__device__ __forceinline__ void cp16(void* dst, const void* src) {
    unsigned d = (unsigned)__cvta_generic_to_shared(dst);
    asm volatile("cp.async.cg.shared.global [%0], [%1], 16;" :: "r"(d), "l"(src));
}
__device__ __forceinline__ unsigned h2u(__half2 h) { return *(unsigned*)&h; }
__device__ __forceinline__ unsigned ex2h2(unsigned x) {
    unsigned y;
    asm("ex2.approx.f16x2 %0, %1;" : "=r"(y) : "r"(x));
    return y;
}
__device__ __forceinline__ unsigned addh2(unsigned a, unsigned b) {
    unsigned y;
    asm("add.f16x2 %0, %1, %2;" : "=r"(y) : "r"(a), "r"(b));
    return y;
}
#define CP_COMMIT() asm volatile("cp.async.commit_group;")
#define CP_WAIT0()  asm volatile("cp.async.wait_group 0;")

#define ONES2 0x3C003C00u   // half2(1.0, 1.0)

// ---------------------------------------------------------------------------
// fp32 -> fp16 convert: z=0 -> X, z=1..3 -> Wq/Wk/Wv
// ---------------------------------------------------------------------------
__global__ __launch_bounds__(256) void convert_kernel(
    const float* __restrict__ X,  const float* __restrict__ Wq,
    const float* __restrict__ Wk, const float* __restrict__ Wv)
{
    const int z = blockIdx.z;
    const float* src;
    __half* dst;
    int n4;
    if (z == 0) { src = X; dst = g_Xh; n4 = BB * SS * DD / 4; }
    else {
        src = (z == 1) ? Wq : ((z == 2) ? Wk : Wv);
        dst = g_Wh + (size_t)(z - 1) * DD * DD;
        n4  = DD * DD / 4;
    }
    for (int i = blockIdx.x * blockDim.x + threadIdx.x; i < n4;
         i += gridDim.x * blockDim.x) {
        float4 v = ((const float4*)src)[i];
        __half2 h0 = __floats2half2_rn(v.x, v.y);
        __half2 h1 = __floats2half2_rn(v.z, v.w);
        uint2 o; o.x = *(unsigned*)&h0; o.y = *(unsigned*)&h1;
        ((uint2*)dst)[i] = o;
    }
}

// ---------------------------------------------------------------------------
// QKV projection, fp16 MMA (fp32 acc) + ldmatrix + cp.async double buffer.
// Block 128m x 128n, 4 warps (2m x 2n), warp tile 64m x 64n. K chunks of 64.
// t==1 (K): epilogue scales rows by 0.125*log2e*click[b,s] (softmax uses ex2).
// ---------------------------------------------------------------------------
#define QKV_STRIDE 72
__global__ __launch_bounds__(128) void qkv_kernel(
    const float* __restrict__ bq, const float* __restrict__ bk,
    const float* __restrict__ bv, const float* __restrict__ click)
{
    extern __shared__ __half smh[];
    __half* Xs = smh;                       // [2][128*72]
    __half* Ws = smh + 2 * 128 * QKV_STRIDE;

    const int t  = blockIdx.z;
    const float* bias = (t == 0) ? bq : ((t == 1) ? bk : bv);
    const __half* Xg = g_Xh;
    const __half* Wg = g_Wh + (size_t)t * DD * DD;

    const int n0 = blockIdx.x * 128;
    const int m0 = blockIdx.y * 128;

    const int tid  = threadIdx.x;
    const int w    = tid >> 5;
    const int lane = tid & 31;
    const int g    = lane >> 2;
    const int tg   = lane & 3;
    const int wm   = (w & 1) * 64;          // warp m offset (2x2 warp grid)
    const int wn   = (w >> 1) * 64;         // warp n offset

    const int rA = lane & 15;
    const int cA = (lane >> 4) * 8;
    const int rB = (lane & 7) + ((lane & 16) ? 8 : 0);
    const int cB = (lane & 8) ? 8 : 0;

    float acc[4][8][4] = {};                // 4 m-frags x 8 n-frags

    {   // prologue: stage chunk 0
        #pragma unroll
        for (int i = 0; i < 8; i++) {
            int f = tid + i * 128;          // 0..1023
            int r = f >> 3, c8 = (f & 7) * 8;
            cp16(&Xs[r * QKV_STRIDE + c8], &Xg[(size_t)(m0 + r) * DD + c8]);
            cp16(&Ws[r * QKV_STRIDE + c8], &Wg[(size_t)(n0 + r) * DD + c8]);
        }
        CP_COMMIT();
    }

    int p = 0;
    for (int ch = 0; ch < 12; ch++) {
        CP_WAIT0();
        __syncthreads();
        if (ch < 11) {
            const int k0 = (ch + 1) * 64;
            __half* Xd = Xs + (p ^ 1) * 128 * QKV_STRIDE;
            __half* Wd = Ws + (p ^ 1) * 128 * QKV_STRIDE;
            #pragma unroll
            for (int i = 0; i < 8; i++) {
                int f = tid + i * 128;
                int r = f >> 3, c8 = (f & 7) * 8;
                cp16(&Xd[r * QKV_STRIDE + c8], &Xg[(size_t)(m0 + r) * DD + k0 + c8]);
                cp16(&Wd[r * QKV_STRIDE + c8], &Wg[(size_t)(n0 + r) * DD + k0 + c8]);
            }
            CP_COMMIT();
        }

        const __half* Xp = Xs + p * 128 * QKV_STRIDE;
        const __half* Wp = Ws + p * 128 * QKV_STRIDE;
        #pragma unroll
        for (int kc = 0; kc < 4; kc++) {
            const int kk = kc * 16;
            unsigned a[4][4];
            #pragma unroll
            for (int mi = 0; mi < 4; mi++)
                ldsm4(a[mi], &Xp[(wm + mi * 16 + rA) * QKV_STRIDE + kk + cA]);
            #pragma unroll
            for (int ntp = 0; ntp < 4; ntp++) {
                unsigned B[4];
                ldsm4(B, &Wp[(wn + ntp * 16 + rB) * QKV_STRIDE + kk + cB]);
                #pragma unroll
                for (int mi = 0; mi < 4; mi++) {
                    mma16(acc[mi][ntp * 2],     a[mi], B[0], B[1]);
                    mma16(acc[mi][ntp * 2 + 1], a[mi], B[2], B[3]);
                }
            }
        }
        p ^= 1;
    }

    // epilogue: s-major fp16 stores; K rows scaled by 0.125*log2e*click
    __half* dst = (t == 0) ? g_Q : ((t == 1) ? g_K : g_V);
    #pragma unroll
    for (int mi = 0; mi < 4; mi++) {
        const int r0    = m0 + wm + mi * 16 + g;
        const int batch = r0 >> 10;
        const int s0    = r0 & 1023;
        const int s1    = s0 + 8;
        float f0s = 1.f, f1s = 1.f;
        if (t == 1) {
            f0s = (0.125f * LOG2E) * click[batch * SS + s0];
            f1s = (0.125f * LOG2E) * click[batch * SS + s1];
        }
        #pragma unroll
        for (int nt = 0; nt < 8; nt++) {
            const int col = n0 + wn + nt * 8 + 2 * tg;
            const int h   = col >> 6;
            const int d   = col & 63;
            const int bh  = batch * HH + h;
            const float b0v = bias[col], b1v = bias[col + 1];
            *(__half2*)&dst[((size_t)bh * SS + s0) * DHD + d] =
                __floats2half2_rn((acc[mi][nt][0] + b0v) * f0s,
                                  (acc[mi][nt][1] + b1v) * f0s);
            *(__half2*)&dst[((size_t)bh * SS + s1) * DHD + d] =
                __floats2half2_rn((acc[mi][nt][2] + b0v) * f1s,
                                  (acc[mi][nt][3] + b1v) * f1s);
        }
    }
}

// ---------------------------------------------------------------------------
// Flash attention: 256 thr (8 warps) per block = (bh, 256 q rows); warp owns
// 32 q rows. Each K/V tile staged ONCE serves 8 warps (2x amortization vs
// round 12). No online max; QK in fp16 accumulators; P = ex2.f16x2(score +
// mask) directly forms PV A-frags; row sums via ones-matrix MMA; PV fp32 acc.
// ---------------------------------------------------------------------------
#define AT_STRIDE 72
__global__ __launch_bounds__(256) void attn_kernel(
    const float* __restrict__ mask,
    float* __restrict__ out)
{
    __shared__ __half Ks[2][64 * AT_STRIDE];
    __shared__ __half Vs[2][64 * AT_STRIDE];
    __shared__ unsigned mkS[2][32];            // half2-packed log2e*mask pairs

    const int bh = blockIdx.y;
    const int b  = bh / HH;
    const int h  = bh % HH;
    const int q0 = blockIdx.x * 256;

    const int tid  = threadIdx.x;
    const int w    = tid >> 5;
    const int lane = tid & 31;
    const int g    = lane >> 2;
    const int tg   = lane & 3;
    const int qw   = w * 32;

    const int rB = (lane & 7) + ((lane & 16) ? 8 : 0);      // QK B (non-trans)
    const int cB = (lane & 8) ? 8 : 0;
    const int rT = (lane & 7) + ((lane & 8) ? 8 : 0);       // PV B (trans)
    const int cT = (lane & 16) ? 8 : 0;

    // Q fragments once from global: 2 m-frags x 4 k-chunks
    unsigned Qa[2][4][4];
    #pragma unroll
    for (int mi = 0; mi < 2; mi++) {
        const size_t qb0 = ((size_t)bh * SS + q0 + qw + mi * 16 + g) * DHD;
        const size_t qb1 = qb0 + 8 * DHD;
        #pragma unroll
        for (int kc = 0; kc < 4; kc++) {
            const int kk = kc * 16;
            Qa[mi][kc][0] = *(const unsigned*)&g_Q[qb0 + kk + 2 * tg];
            Qa[mi][kc][1] = *(const unsigned*)&g_Q[qb1 + kk + 2 * tg];
            Qa[mi][kc][2] = *(const unsigned*)&g_Q[qb0 + kk + 2 * tg + 8];
            Qa[mi][kc][3] = *(const unsigned*)&g_Q[qb1 + kk + 2 * tg + 8];
        }
    }

    {   // prologue: stage tile 0 (K+V = 1024 segs, 256 thr -> 2 iters each matrix)
        #pragma unroll
        for (int i = 0; i < 2; i++) {
            int f = tid + i * 256;               // 0..511
            int r = f >> 3, c8 = (f & 7) * 8;
            cp16(&Ks[0][r * AT_STRIDE + c8], &g_K[((size_t)bh * SS + r) * DHD + c8]);
            cp16(&Vs[0][r * AT_STRIDE + c8], &g_V[((size_t)bh * SS + r) * DHD + c8]);
        }
        CP_COMMIT();
    }
    unsigned mkreg = 0;
    if (tid < 32) {
        float2 mv = *(const float2*)&mask[b * SS + 2 * tid];
        mkreg = h2u(__floats2half2_rn(LOG2E * mv.x, LOG2E * mv.y));
    }

    float o[2][8][4] = {};
    float ol[2][4] = {};                       // ones-MMA row-sum accumulators

    int p = 0;
    for (int kt = 0; kt < 16; kt++) {
        CP_WAIT0();
        if (tid < 32) mkS[p][tid] = mkreg;
        __syncthreads();

        if (kt < 15) {
            const int k0 = (kt + 1) * 64;
            #pragma unroll
            for (int i = 0; i < 2; i++) {
                int f = tid + i * 256;
                int r = f >> 3, c8 = (f & 7) * 8;
                cp16(&Ks[p ^ 1][r * AT_STRIDE + c8],
                     &g_K[((size_t)bh * SS + k0 + r) * DHD + c8]);
                cp16(&Vs[p ^ 1][r * AT_STRIDE + c8],
                     &g_V[((size_t)bh * SS + k0 + r) * DHD + c8]);
            }
            CP_COMMIT();
            if (tid < 32) {
                float2 mv = *(const float2*)&mask[b * SS + k0 + 2 * tid];
                mkreg = h2u(__floats2half2_rn(LOG2E * mv.x, LOG2E * mv.y));
            }
        }

        const __half* Kp = Ks[p];
        const __half* Vp = Vs[p];

        // S' = Q K^T, fp16 accumulators (scores packed half2; K pre-scaled)
        unsigned scH[2][8][2] = {};
        #pragma unroll
        for (int kc = 0; kc < 4; kc++) {
            const int kk = kc * 16;
            #pragma unroll
            for (int ntp = 0; ntp < 4; ntp++) {
                unsigned B[4];
                ldsm4(B, &Kp[(ntp * 16 + rB) * AT_STRIDE + kk + cB]);
                #pragma unroll
                for (int mi = 0; mi < 2; mi++) {
                    mma16h(scH[mi][ntp * 2],     Qa[mi][kc], B[0], B[1]);
                    mma16h(scH[mi][ntp * 2 + 1], Qa[mi][kc], B[2], B[3]);
                }
            }
        }

        // P = exp2(S' + mask'), fully packed (in place -> PV A-fragments)
        #pragma unroll
        for (int mi = 0; mi < 2; mi++) {
            #pragma unroll
            for (int nt = 0; nt < 8; nt++) {
                const unsigned m2 = mkS[p][nt * 4 + tg];
                scH[mi][nt][0] = ex2h2(addh2(scH[mi][nt][0], m2));
                scH[mi][nt][1] = ex2h2(addh2(scH[mi][nt][1], m2));
            }
        }

        // O += P V ; l += P * ones  (both fp32 acc)
        #pragma unroll
        for (int kc = 0; kc < 4; kc++) {
            const int kk = kc * 16;
            unsigned pa[2][4];
            #pragma unroll
            for (int mi = 0; mi < 2; mi++) {
                pa[mi][0] = scH[mi][2 * kc][0];
                pa[mi][1] = scH[mi][2 * kc][1];
                pa[mi][2] = scH[mi][2 * kc + 1][0];
                pa[mi][3] = scH[mi][2 * kc + 1][1];
                mma16(ol[mi], pa[mi], ONES2, ONES2);   // row sums
            }
            #pragma unroll
            for (int ntp = 0; ntp < 4; ntp++) {
                unsigned B[4];
                ldsm4t(B, &Vp[(kk + rT) * AT_STRIDE + ntp * 16 + cT]);
                #pragma unroll
                for (int mi = 0; mi < 2; mi++) {
                    mma16(o[mi][ntp * 2],     pa[mi], B[0], B[1]);
                    mma16(o[mi][ntp * 2 + 1], pa[mi], B[2], B[3]);
                }
            }
        }
        p ^= 1;
    }

    // epilogue: ol[mi][0] = full row sum (row g), ol[mi][2] = row g+8
    #pragma unroll
    for (int mi = 0; mi < 2; mi++) {
        const float inv0 = 1.f / ol[mi][0];
        const float inv1 = 1.f / ol[mi][2];
        const int s0 = q0 + qw + mi * 16 + g;
        const int s1 = s0 + 8;
        #pragma unroll
        for (int nt = 0; nt < 8; nt++) {
            const int d = nt * 8 + 2 * tg;
            *(float2*)(out + ((size_t)(b * SS + s0)) * DD + h * DHD + d) =
                make_float2(o[mi][nt][0] * inv0, o[mi][nt][1] * inv0);
            *(float2*)(out + ((size_t)(b * SS + s1)) * DD + h * DHD + d) =
                make_float2(o[mi][nt][2] * inv1, o[mi][nt][3] * inv1);
        }
    }
}

// ---------------------------------------------------------------------------

extern "C" void kernel_launch(void* const* d_in, const int* in_sizes, int n_in,
                              void* d_out, int out_size)
{
    const float* hidden = (const float*)d_in[0];
    const float* mask   = (const float*)d_in[1];
    const float* click  = (const float*)d_in[2];
    const float* Wq     = (const float*)d_in[3];
    const float* bq     = (const float*)d_in[4];
    const float* Wk     = (const float*)d_in[5];
    const float* bk     = (const float*)d_in[6];
    const float* Wv     = (const float*)d_in[7];
    const float* bv     = (const float*)d_in[8];
    float* out = (float*)d_out;

    dim3 gC(512, 1, 4);
    convert_kernel<<<gC, 256>>>(hidden, Wq, Wk, Wv);

    const int qkv_smem = 4 * 128 * QKV_STRIDE * 2;   // 73728 B
    cudaFuncSetAttribute(qkv_kernel,
                         cudaFuncAttributeMaxDynamicSharedMemorySize, qkv_smem);
    dim3 gA(6, 64, 3);
    qkv_kernel<<<gA, 128, qkv_smem>>>(bq, bk, bv, click);

    dim3 gB(4, 96);
    attn_kernel<<<gB, 256>>>(mask, out);
}

// round 15
// speedup vs baseline: 1.0313x; 1.0313x over previous
#include <cuda_runtime.h>
#include <cuda_fp16.h>
#include <math.h>

#define BB   8
#define SS   1024
#define DD   768
#define HH   12
#define DHD  64
#define BHN  (BB*HH)

#define LOG2E 1.4426950408889634f

// fp16 scratch
__device__ __half g_Xh[BB * SS * DD];          // X, fp16
__device__ __half g_Wh[3 * DD * DD];           // Wq|Wk|Wv, fp16
__device__ __half g_Q [BHN * SS * DHD];        // s-major [bh][s][d]
__device__ __half g_K [BHN * SS * DHD];        // K rows pre-scaled by 0.125*log2e*click
__device__ __half g_V [BHN * SS * DHD];

// ---------------------------------------------------------------------------
// helpers
// ---------------------------------------------------------------------------
__device__ __forceinline__ void mma16(float c[4], const unsigned a[4],
                                      unsigned b0, unsigned b1) {
    asm volatile(
        "mma.sync.aligned.m16n8k16.row.col.f32.f16.f16.f32 "
        "{%0,%1,%2,%3}, {%4,%5,%6,%7}, {%8,%9}, {%0,%1,%2,%3};"
        : "+f"(c[0]), "+f"(c[1]), "+f"(c[2]), "+f"(c[3])
        : "r"(a[0]), "r"(a[1]), "r"(a[2]), "r"(a[3]), "r"(b0), "r"(b1));
}
// fp16 accumulator variant: D/C = 2 packed half2 regs,
// reg0 = (row g, cols 2tg,2tg+1), reg1 = (row g+8, same cols).
__device__ __forceinline__ void mma16h(unsigned c[2], const unsigned a[4],
                                       unsigned b0, unsigned b1) {
    asm volatile(
        "mma.sync.aligned.m16n8k16.row.col.f16.f16.f16.f16 "
        "{%0,%1}, {%2,%3,%4,%5}, {%6,%7}, {%0,%1};"
        : "+r"(c[0]), "+r"(c[1])
        : "r"(a[0]), "r"(a[1]), "r"(a[2]), "r"(a[3]), "r"(b0), "r"(b1));
}
__device__ __forceinline__ void ldsm4(unsigned r[4], const void* p) {
    unsigned a = (unsigned)__cvta_generic_to_shared(p);
    asm volatile("ldmatrix.sync.aligned.m8n8.x4.shared.b16 {%0,%1,%2,%3}, [%4];"
                 : "=r"(r[0]), "=r"(r[1]), "=r"(r[2]), "=r"(r[3]) : "r"(a));
}
__device__ __forceinline__ void ldsm4t(unsigned r[4], const void* p) {
    unsigned a = (unsigned)__cvta_generic_to_shared(p);
    asm volatile("ldmatrix.sync.aligned.m8n8.x4.trans.shared.b16 {%0,%1,%2,%3}, [%4];"
                 : "=r"(r[0]), "=r"(r[1]), "=r"(r[2]), "=r"(r[3]) : "r"(a));
}
__device__ __forceinline__ void cp16(void* dst, const void* src) {
    unsigned d = (unsigned)__cvta_generic_to_shared(dst);
    asm volatile("cp.async.cg.shared.global [%0], [%1], 16;" :: "r"(d), "l"(src));
}
__device__ __forceinline__ unsigned h2u(__half2 h) { return *(unsigned*)&h; }
__device__ __forceinline__ unsigned ex2h2(unsigned x) {
    unsigned y;
    asm("ex2.approx.f16x2 %0, %1;" : "=r"(y) : "r"(x));
    return y;
}
__device__ __forceinline__ unsigned addh2(unsigned a, unsigned b) {
    unsigned y;
    asm("add.f16x2 %0, %1, %2;" : "=r"(y) : "r"(a), "r"(b));
    return y;
}
#define CP_COMMIT() asm volatile("cp.async.commit_group;")
#define CP_WAIT0()  asm volatile("cp.async.wait_group 0;")
#define CP_WAIT1()  asm volatile("cp.async.wait_group 1;")

#define ONES2 0x3C003C00u   // half2(1.0, 1.0)

// ---------------------------------------------------------------------------
// fp32 -> fp16 convert, flattened: ONE float4 per thread (no grid-stride
// loop -> no serialized MLP). Items: X first, then Wq|Wk|Wv.
// ---------------------------------------------------------------------------
#define NX4 (BB * SS * DD / 4)     // 1,572,864
#define NW4 (DD * DD / 4)          //   147,456
#define NCONV (NX4 + 3 * NW4)      // 2,015,232  (= 7872 * 256)

__global__ __launch_bounds__(256) void convert_kernel(
    const float* __restrict__ X,  const float* __restrict__ Wq,
    const float* __restrict__ Wk, const float* __restrict__ Wv)
{
    const int idx = blockIdx.x * 256 + threadIdx.x;
    const float* src;
    __half* dst;
    int i;
    if (idx < NX4) {
        src = X; dst = g_Xh; i = idx;
    } else {
        const int wv = idx - NX4;
        const int z  = wv / NW4;
        i   = wv - z * NW4;
        src = (z == 0) ? Wq : ((z == 1) ? Wk : Wv);
        dst = g_Wh + (size_t)z * (DD * DD);
    }
    float4 v = ((const float4*)src)[i];
    __half2 h0 = __floats2half2_rn(v.x, v.y);
    __half2 h1 = __floats2half2_rn(v.z, v.w);
    uint2 o; o.x = *(unsigned*)&h0; o.y = *(unsigned*)&h1;
    ((uint2*)dst)[i] = o;
}

// ---------------------------------------------------------------------------
// QKV projection (round-12 config), fp16 MMA (fp32 acc) + ldmatrix +
// cp.async double buffer. Block 128m x 128n, 8 warps (4m x 2n), warp tile
// 32m x 64n. K chunks of 64.
// t==1 (K): epilogue scales rows by 0.125*log2e*click[b,s] (softmax uses ex2).
// ---------------------------------------------------------------------------
#define QKV_STRIDE 72
__global__ __launch_bounds__(256) void qkv_kernel(
    const float* __restrict__ bq, const float* __restrict__ bk,
    const float* __restrict__ bv, const float* __restrict__ click)
{
    extern __shared__ __half smh[];
    __half* Xs = smh;                       // [2][128*72]
    __half* Ws = smh + 2 * 128 * QKV_STRIDE;

    const int t  = blockIdx.z;
    const float* bias = (t == 0) ? bq : ((t == 1) ? bk : bv);
    const __half* Xg = g_Xh;
    const __half* Wg = g_Wh + (size_t)t * DD * DD;

    const int n0 = blockIdx.x * 128;
    const int m0 = blockIdx.y * 128;

    const int tid  = threadIdx.x;
    const int w    = tid >> 5;
    const int lane = tid & 31;
    const int g    = lane >> 2;
    const int tg   = lane & 3;
    const int wm   = (w & 3) * 32;
    const int wn   = (w >> 2) * 64;

    const int rA = lane & 15;
    const int cA = (lane >> 4) * 8;
    const int rB = (lane & 7) + ((lane & 16) ? 8 : 0);
    const int cB = (lane & 8) ? 8 : 0;

    float acc[2][8][4] = {};

    {   // prologue: stage chunk 0
        #pragma unroll
        for (int i = 0; i < 4; i++) {
            int f = tid + i * 256;
            int r = f >> 3, c8 = (f & 7) * 8;
            cp16(&Xs[r * QKV_STRIDE + c8], &Xg[(size_t)(m0 + r) * DD + c8]);
            cp16(&Ws[r * QKV_STRIDE + c8], &Wg[(size_t)(n0 + r) * DD + c8]);
        }
        CP_COMMIT();
    }

    int p = 0;
    for (int ch = 0; ch < 12; ch++) {
        CP_WAIT0();
        __syncthreads();
        if (ch < 11) {
            const int k0 = (ch + 1) * 64;
            __half* Xd = Xs + (p ^ 1) * 128 * QKV_STRIDE;
            __half* Wd = Ws + (p ^ 1) * 128 * QKV_STRIDE;
            #pragma unroll
            for (int i = 0; i < 4; i++) {
                int f = tid + i * 256;
                int r = f >> 3, c8 = (f & 7) * 8;
                cp16(&Xd[r * QKV_STRIDE + c8], &Xg[(size_t)(m0 + r) * DD + k0 + c8]);
                cp16(&Wd[r * QKV_STRIDE + c8], &Wg[(size_t)(n0 + r) * DD + k0 + c8]);
            }
            CP_COMMIT();
        }

        const __half* Xp = Xs + p * 128 * QKV_STRIDE;
        const __half* Wp = Ws + p * 128 * QKV_STRIDE;
        #pragma unroll
        for (int kc = 0; kc < 4; kc++) {
            const int kk = kc * 16;
            unsigned a0[4], a1[4];
            ldsm4(a0, &Xp[(wm + rA)      * QKV_STRIDE + kk + cA]);
            ldsm4(a1, &Xp[(wm + 16 + rA) * QKV_STRIDE + kk + cA]);
            #pragma unroll
            for (int ntp = 0; ntp < 4; ntp++) {
                unsigned B[4];
                ldsm4(B, &Wp[(wn + ntp * 16 + rB) * QKV_STRIDE + kk + cB]);
                mma16(acc[0][ntp * 2],     a0, B[0], B[1]);
                mma16(acc[0][ntp * 2 + 1], a0, B[2], B[3]);
                mma16(acc[1][ntp * 2],     a1, B[0], B[1]);
                mma16(acc[1][ntp * 2 + 1], a1, B[2], B[3]);
            }
        }
        p ^= 1;
    }

    // epilogue: s-major fp16 stores; K rows scaled by 0.125*log2e*click
    __half* dst = (t == 0) ? g_Q : ((t == 1) ? g_K : g_V);
    #pragma unroll
    for (int mi = 0; mi < 2; mi++) {
        const int r0    = m0 + wm + mi * 16 + g;
        const int batch = r0 >> 10;
        const int s0    = r0 & 1023;
        const int s1    = s0 + 8;
        float f0s = 1.f, f1s = 1.f;
        if (t == 1) {
            f0s = (0.125f * LOG2E) * click[batch * SS + s0];
            f1s = (0.125f * LOG2E) * click[batch * SS + s1];
        }
        #pragma unroll
        for (int nt = 0; nt < 8; nt++) {
            const int col = n0 + wn + nt * 8 + 2 * tg;
            const int h   = col >> 6;
            const int d   = col & 63;
            const int bh  = batch * HH + h;
            const float b0v = bias[col], b1v = bias[col + 1];
            *(__half2*)&dst[((size_t)bh * SS + s0) * DHD + d] =
                __floats2half2_rn((acc[mi][nt][0] + b0v) * f0s,
                                  (acc[mi][nt][1] + b1v) * f0s);
            *(__half2*)&dst[((size_t)bh * SS + s1) * DHD + d] =
                __floats2half2_rn((acc[mi][nt][2] + b0v) * f1s,
                                  (acc[mi][nt][3] + b1v) * f1s);
        }
    }
}

// ---------------------------------------------------------------------------
// Flash attention (round-12 math) with TRIPLE-buffered K/V (prefetch
// distance 2 -> wait cost ~0 at the tile boundary). No online max; QK in
// fp16 accumulators; P = ex2.f16x2(score + mask) directly forms PV A-frags;
// row sums via ones-matrix MMA; PV fp32 acc.
// 128 thr (4 warps); block = (bh, 128 q rows); warp owns 32 q rows.
// ---------------------------------------------------------------------------
#define AT_STRIDE 72
#define AT_TILE   (64 * AT_STRIDE)
__global__ __launch_bounds__(128) void attn_kernel(
    const float* __restrict__ mask,
    float* __restrict__ out)
{
    extern __shared__ __half ash[];
    __half*   Ks  = ash;                    // [3][64*72]
    __half*   Vs  = ash + 3 * AT_TILE;      // [3][64*72]
    unsigned* mkS = (unsigned*)(ash + 6 * AT_TILE);   // [3][32]

    const int bh = blockIdx.y;
    const int b  = bh / HH;
    const int h  = bh % HH;
    const int q0 = blockIdx.x * 128;

    const int tid  = threadIdx.x;
    const int w    = tid >> 5;
    const int lane = tid & 31;
    const int g    = lane >> 2;
    const int tg   = lane & 3;
    const int qw   = w * 32;

    const int rB = (lane & 7) + ((lane & 16) ? 8 : 0);      // QK B (non-trans)
    const int cB = (lane & 8) ? 8 : 0;
    const int rT = (lane & 7) + ((lane & 8) ? 8 : 0);       // PV B (trans)
    const int cT = (lane & 16) ? 8 : 0;

    // Q fragments once from global: 2 m-frags x 4 k-chunks
    unsigned Qa[2][4][4];
    #pragma unroll
    for (int mi = 0; mi < 2; mi++) {
        const size_t qb0 = ((size_t)bh * SS + q0 + qw + mi * 16 + g) * DHD;
        const size_t qb1 = qb0 + 8 * DHD;
        #pragma unroll
        for (int kc = 0; kc < 4; kc++) {
            const int kk = kc * 16;
            Qa[mi][kc][0] = *(const unsigned*)&g_Q[qb0 + kk + 2 * tg];
            Qa[mi][kc][1] = *(const unsigned*)&g_Q[qb1 + kk + 2 * tg];
            Qa[mi][kc][2] = *(const unsigned*)&g_Q[qb0 + kk + 2 * tg + 8];
            Qa[mi][kc][3] = *(const unsigned*)&g_Q[qb1 + kk + 2 * tg + 8];
        }
    }

    // prologue: stage tiles 0 and 1 (two commit groups)
    #pragma unroll
    for (int tpre = 0; tpre < 2; tpre++) {
        const int k0 = tpre * 64;
        __half* Kd = Ks + tpre * AT_TILE;
        __half* Vd = Vs + tpre * AT_TILE;
        #pragma unroll
        for (int i = 0; i < 4; i++) {
            int f = tid + i * 128;
            int r = f >> 3, c8 = (f & 7) * 8;
            cp16(&Kd[r * AT_STRIDE + c8], &g_K[((size_t)bh * SS + k0 + r) * DHD + c8]);
            cp16(&Vd[r * AT_STRIDE + c8], &g_V[((size_t)bh * SS + k0 + r) * DHD + c8]);
        }
        CP_COMMIT();
    }
    unsigned mkreg = 0;
    if (tid < 32) {
        float2 mv = *(const float2*)&mask[b * SS + 2 * tid];
        mkreg = h2u(__floats2half2_rn(LOG2E * mv.x, LOG2E * mv.y));
    }

    float o[2][8][4] = {};
    float ol[2][4] = {};                       // ones-MMA row-sum accumulators

    for (int kt = 0; kt < 16; kt++) {
        const int p = kt % 3;
        if (kt < 14) CP_WAIT1(); else CP_WAIT0();   // tile kt arrived
        if (tid < 32) mkS[p * 32 + tid] = mkreg;
        __syncthreads();

        if (kt < 14) {
            const int k0 = (kt + 2) * 64;
            const int q = (kt + 2) % 3;
            __half* Kd = Ks + q * AT_TILE;
            __half* Vd = Vs + q * AT_TILE;
            #pragma unroll
            for (int i = 0; i < 4; i++) {
                int f = tid + i * 128;
                int r = f >> 3, c8 = (f & 7) * 8;
                cp16(&Kd[r * AT_STRIDE + c8],
                     &g_K[((size_t)bh * SS + k0 + r) * DHD + c8]);
                cp16(&Vd[r * AT_STRIDE + c8],
                     &g_V[((size_t)bh * SS + k0 + r) * DHD + c8]);
            }
            CP_COMMIT();
        }
        if (kt < 15 && tid < 32) {
            float2 mv = *(const float2*)&mask[b * SS + (kt + 1) * 64 + 2 * tid];
            mkreg = h2u(__floats2half2_rn(LOG2E * mv.x, LOG2E * mv.y));
        }

        const __half* Kp = Ks + p * AT_TILE;
        const __half* Vp = Vs + p * AT_TILE;

        // S' = Q K^T, fp16 accumulators (scores packed half2; K pre-scaled)
        unsigned scH[2][8][2] = {};
        #pragma unroll
        for (int kc = 0; kc < 4; kc++) {
            const int kk = kc * 16;
            #pragma unroll
            for (int ntp = 0; ntp < 4; ntp++) {
                unsigned B[4];
                ldsm4(B, &Kp[(ntp * 16 + rB) * AT_STRIDE + kk + cB]);
                #pragma unroll
                for (int mi = 0; mi < 2; mi++) {
                    mma16h(scH[mi][ntp * 2],     Qa[mi][kc], B[0], B[1]);
                    mma16h(scH[mi][ntp * 2 + 1], Qa[mi][kc], B[2], B[3]);
                }
            }
        }

        // P = exp2(S' + mask'), fully packed (in place -> PV A-fragments)
        #pragma unroll
        for (int mi = 0; mi < 2; mi++) {
            #pragma unroll
            for (int nt = 0; nt < 8; nt++) {
                const unsigned m2 = mkS[p * 32 + nt * 4 + tg];
                scH[mi][nt][0] = ex2h2(addh2(scH[mi][nt][0], m2));
                scH[mi][nt][1] = ex2h2(addh2(scH[mi][nt][1], m2));
            }
        }

        // O += P V ; l += P * ones  (both fp32 acc)
        #pragma unroll
        for (int kc = 0; kc < 4; kc++) {
            const int kk = kc * 16;
            unsigned pa[2][4];
            #pragma unroll
            for (int mi = 0; mi < 2; mi++) {
                pa[mi][0] = scH[mi][2 * kc][0];
                pa[mi][1] = scH[mi][2 * kc][1];
                pa[mi][2] = scH[mi][2 * kc + 1][0];
                pa[mi][3] = scH[mi][2 * kc + 1][1];
                mma16(ol[mi], pa[mi], ONES2, ONES2);   // row sums
            }
            #pragma unroll
            for (int ntp = 0; ntp < 4; ntp++) {
                unsigned B[4];
                ldsm4t(B, &Vp[(kk + rT) * AT_STRIDE + ntp * 16 + cT]);
                #pragma unroll
                for (int mi = 0; mi < 2; mi++) {
                    mma16(o[mi][ntp * 2],     pa[mi], B[0], B[1]);
                    mma16(o[mi][ntp * 2 + 1], pa[mi], B[2], B[3]);
                }
            }
        }
    }

    // epilogue: ol[mi][0] = full row sum (row g), ol[mi][2] = row g+8
    #pragma unroll
    for (int mi = 0; mi < 2; mi++) {
        const float inv0 = 1.f / ol[mi][0];
        const float inv1 = 1.f / ol[mi][2];
        const int s0 = q0 + qw + mi * 16 + g;
        const int s1 = s0 + 8;
        #pragma unroll
        for (int nt = 0; nt < 8; nt++) {
            const int d = nt * 8 + 2 * tg;
            *(float2*)(out + ((size_t)(b * SS + s0)) * DD + h * DHD + d) =
                make_float2(o[mi][nt][0] * inv0, o[mi][nt][1] * inv0);
            *(float2*)(out + ((size_t)(b * SS + s1)) * DD + h * DHD + d) =
                make_float2(o[mi][nt][2] * inv1, o[mi][nt][3] * inv1);
        }
    }
}

// ---------------------------------------------------------------------------

extern "C" void kernel_launch(void* const* d_in, const int* in_sizes, int n_in,
                              void* d_out, int out_size)
{
    const float* hidden = (const float*)d_in[0];
    const float* mask   = (const float*)d_in[1];
    const float* click  = (const float*)d_in[2];
    const float* Wq     = (const float*)d_in[3];
    const float* bq     = (const float*)d_in[4];
    const float* Wk     = (const float*)d_in[5];
    const float* bk     = (const float*)d_in[6];
    const float* Wv     = (const float*)d_in[7];
    const float* bv     = (const float*)d_in[8];
    float* out = (float*)d_out;

    convert_kernel<<<NCONV / 256, 256>>>(hidden, Wq, Wk, Wv);

    const int qkv_smem = 4 * 128 * QKV_STRIDE * 2;   // 73728 B
    cudaFuncSetAttribute(qkv_kernel,
                         cudaFuncAttributeMaxDynamicSharedMemorySize, qkv_smem);
    dim3 gA(6, 64, 3);
    qkv_kernel<<<gA, 256, qkv_smem>>>(bq, bk, bv, click);

    const int attn_smem = 6 * AT_TILE * 2 + 3 * 32 * 4;   // 55680 B
    cudaFuncSetAttribute(attn_kernel,
                         cudaFuncAttributeMaxDynamicSharedMemorySize, attn_smem);
    dim3 gB(8, 96);
    attn_kernel<<<gB, 128, attn_smem>>>(mask, out);
}

// round 16
// speedup vs baseline: 1.0580x; 1.0259x over previous
#include <cuda_runtime.h>
#include <cuda_fp16.h>
#include <math.h>

#define BB   8
#define SS   1024
#define DD   768
#define HH   12
#define DHD  64
#define BHN  (BB*HH)

#define LOG2E 1.4426950408889634f

// fp16 scratch
__device__ __half g_Xh[BB * SS * DD];          // X, fp16
__device__ __half g_Wh[3 * DD * DD];           // Wq|Wk|Wv, fp16
__device__ __half g_Q [BHN * SS * DHD];        // s-major [bh][s][d]
__device__ __half g_K [BHN * SS * DHD];        // K rows pre-scaled by 0.125*log2e*click
__device__ __half g_V [BHN * SS * DHD];

// ---------------------------------------------------------------------------
// helpers
// ---------------------------------------------------------------------------
__device__ __forceinline__ void mma16(float c[4], const unsigned a[4],
                                      unsigned b0, unsigned b1) {
    asm volatile(
        "mma.sync.aligned.m16n8k16.row.col.f32.f16.f16.f32 "
        "{%0,%1,%2,%3}, {%4,%5,%6,%7}, {%8,%9}, {%0,%1,%2,%3};"
        : "+f"(c[0]), "+f"(c[1]), "+f"(c[2]), "+f"(c[3])
        : "r"(a[0]), "r"(a[1]), "r"(a[2]), "r"(a[3]), "r"(b0), "r"(b1));
}
// fp16 accumulator variant: D/C = 2 packed half2 regs,
// reg0 = (row g, cols 2tg,2tg+1), reg1 = (row g+8, same cols).
__device__ __forceinline__ void mma16h(unsigned c[2], const unsigned a[4],
                                       unsigned b0, unsigned b1) {
    asm volatile(
        "mma.sync.aligned.m16n8k16.row.col.f16.f16.f16.f16 "
        "{%0,%1}, {%2,%3,%4,%5}, {%6,%7}, {%0,%1};"
        : "+r"(c[0]), "+r"(c[1])
        : "r"(a[0]), "r"(a[1]), "r"(a[2]), "r"(a[3]), "r"(b0), "r"(b1));
}
__device__ __forceinline__ void ldsm4(unsigned r[4], const void* p) {
    unsigned a = (unsigned)__cvta_generic_to_shared(p);
    asm volatile("ldmatrix.sync.aligned.m8n8.x4.shared.b16 {%0,%1,%2,%3}, [%4];"
                 : "=r"(r[0]), "=r"(r[1]), "=r"(r[2]), "=r"(r[3]) : "r"(a));
}
__device__ __forceinline__ void ldsm4t(unsigned r[4], const void* p) {
    unsigned a = (unsigned)__cvta_generic_to_shared(p);
    asm volatile("ldmatrix.sync.aligned.m8n8.x4.trans.shared.b16 {%0,%1,%2,%3}, [%4];"
                 : "=r"(r[0]), "=r"(r[1]), "=r"(r[2]), "=r"(r[3]) : "r"(a));
}
__device__ __forceinline__ void cp16(void* dst, const void* src) {
    unsigned d = (unsigned)__cvta_generic_to_shared(dst);
    asm volatile("cp.async.cg.shared.global [%0], [%1], 16;" :: "r"(d), "l"(src));
}
__device__ __forceinline__ unsigned h2u(__half2 h) { return *(unsigned*)&h; }
__device__ __forceinline__ unsigned ex2h2(unsigned x) {
    unsigned y;
    asm("ex2.approx.f16x2 %0, %1;" : "=r"(y) : "r"(x));
    return y;
}
__device__ __forceinline__ unsigned addh2(unsigned a, unsigned b) {
    unsigned y;
    asm("add.f16x2 %0, %1, %2;" : "=r"(y) : "r"(a), "r"(b));
    return y;
}
#define CP_COMMIT() asm volatile("cp.async.commit_group;")
#define CP_WAIT0()  asm volatile("cp.async.wait_group 0;")

#define ONES2 0x3C003C00u   // half2(1.0, 1.0)

// ---------------------------------------------------------------------------
// fp32 -> fp16 convert, flattened: ONE float4 per thread.
// Items: X first, then Wq|Wk|Wv.
// ---------------------------------------------------------------------------
#define NX4 (BB * SS * DD / 4)     // 1,572,864
#define NW4 (DD * DD / 4)          //   147,456
#define NCONV (NX4 + 3 * NW4)      // 2,015,232  (= 7872 * 256)

__global__ __launch_bounds__(256) void convert_kernel(
    const float* __restrict__ X,  const float* __restrict__ Wq,
    const float* __restrict__ Wk, const float* __restrict__ Wv)
{
    const int idx = blockIdx.x * 256 + threadIdx.x;
    const float* src;
    __half* dst;
    int i;
    if (idx < NX4) {
        src = X; dst = g_Xh; i = idx;
    } else {
        const int wv = idx - NX4;
        const int z  = wv / NW4;
        i   = wv - z * NW4;
        src = (z == 0) ? Wq : ((z == 1) ? Wk : Wv);
        dst = g_Wh + (size_t)z * (DD * DD);
    }
    float4 v = ((const float4*)src)[i];
    __half2 h0 = __floats2half2_rn(v.x, v.y);
    __half2 h1 = __floats2half2_rn(v.z, v.w);
    uint2 o; o.x = *(unsigned*)&h0; o.y = *(unsigned*)&h1;
    ((uint2*)dst)[i] = o;
}

// ---------------------------------------------------------------------------
// QKV projection (round-12 config), fp16 MMA (fp32 acc) + ldmatrix +
// cp.async double buffer. Block 128m x 128n, 8 warps (4m x 2n), warp tile
// 32m x 64n. K chunks of 64.
// t==1 (K): epilogue scales rows by 0.125*log2e*click[b,s] (softmax uses ex2).
// ---------------------------------------------------------------------------
#define QKV_STRIDE 72
__global__ __launch_bounds__(256) void qkv_kernel(
    const float* __restrict__ bq, const float* __restrict__ bk,
    const float* __restrict__ bv, const float* __restrict__ click)
{
    extern __shared__ __half smh[];
    __half* Xs = smh;                       // [2][128*72]
    __half* Ws = smh + 2 * 128 * QKV_STRIDE;

    const int t  = blockIdx.z;
    const float* bias = (t == 0) ? bq : ((t == 1) ? bk : bv);
    const __half* Xg = g_Xh;
    const __half* Wg = g_Wh + (size_t)t * DD * DD;

    const int n0 = blockIdx.x * 128;
    const int m0 = blockIdx.y * 128;

    const int tid  = threadIdx.x;
    const int w    = tid >> 5;
    const int lane = tid & 31;
    const int g    = lane >> 2;
    const int tg   = lane & 3;
    const int wm   = (w & 3) * 32;
    const int wn   = (w >> 2) * 64;

    const int rA = lane & 15;
    const int cA = (lane >> 4) * 8;
    const int rB = (lane & 7) + ((lane & 16) ? 8 : 0);
    const int cB = (lane & 8) ? 8 : 0;

    float acc[2][8][4] = {};

    {   // prologue: stage chunk 0
        #pragma unroll
        for (int i = 0; i < 4; i++) {
            int f = tid + i * 256;
            int r = f >> 3, c8 = (f & 7) * 8;
            cp16(&Xs[r * QKV_STRIDE + c8], &Xg[(size_t)(m0 + r) * DD + c8]);
            cp16(&Ws[r * QKV_STRIDE + c8], &Wg[(size_t)(n0 + r) * DD + c8]);
        }
        CP_COMMIT();
    }

    int p = 0;
    for (int ch = 0; ch < 12; ch++) {
        CP_WAIT0();
        __syncthreads();
        if (ch < 11) {
            const int k0 = (ch + 1) * 64;
            __half* Xd = Xs + (p ^ 1) * 128 * QKV_STRIDE;
            __half* Wd = Ws + (p ^ 1) * 128 * QKV_STRIDE;
            #pragma unroll
            for (int i = 0; i < 4; i++) {
                int f = tid + i * 256;
                int r = f >> 3, c8 = (f & 7) * 8;
                cp16(&Xd[r * QKV_STRIDE + c8], &Xg[(size_t)(m0 + r) * DD + k0 + c8]);
                cp16(&Wd[r * QKV_STRIDE + c8], &Wg[(size_t)(n0 + r) * DD + k0 + c8]);
            }
            CP_COMMIT();
        }

        const __half* Xp = Xs + p * 128 * QKV_STRIDE;
        const __half* Wp = Ws + p * 128 * QKV_STRIDE;
        #pragma unroll
        for (int kc = 0; kc < 4; kc++) {
            const int kk = kc * 16;
            unsigned a0[4], a1[4];
            ldsm4(a0, &Xp[(wm + rA)      * QKV_STRIDE + kk + cA]);
            ldsm4(a1, &Xp[(wm + 16 + rA) * QKV_STRIDE + kk + cA]);
            #pragma unroll
            for (int ntp = 0; ntp < 4; ntp++) {
                unsigned B[4];
                ldsm4(B, &Wp[(wn + ntp * 16 + rB) * QKV_STRIDE + kk + cB]);
                mma16(acc[0][ntp * 2],     a0, B[0], B[1]);
                mma16(acc[0][ntp * 2 + 1], a0, B[2], B[3]);
                mma16(acc[1][ntp * 2],     a1, B[0], B[1]);
                mma16(acc[1][ntp * 2 + 1], a1, B[2], B[3]);
            }
        }
        p ^= 1;
    }

    // epilogue: s-major fp16 stores; K rows scaled by 0.125*log2e*click
    __half* dst = (t == 0) ? g_Q : ((t == 1) ? g_K : g_V);
    #pragma unroll
    for (int mi = 0; mi < 2; mi++) {
        const int r0    = m0 + wm + mi * 16 + g;
        const int batch = r0 >> 10;
        const int s0    = r0 & 1023;
        const int s1    = s0 + 8;
        float f0s = 1.f, f1s = 1.f;
        if (t == 1) {
            f0s = (0.125f * LOG2E) * click[batch * SS + s0];
            f1s = (0.125f * LOG2E) * click[batch * SS + s1];
        }
        #pragma unroll
        for (int nt = 0; nt < 8; nt++) {
            const int col = n0 + wn + nt * 8 + 2 * tg;
            const int h   = col >> 6;
            const int d   = col & 63;
            const int bh  = batch * HH + h;
            const float b0v = bias[col], b1v = bias[col + 1];
            *(__half2*)&dst[((size_t)bh * SS + s0) * DHD + d] =
                __floats2half2_rn((acc[mi][nt][0] + b0v) * f0s,
                                  (acc[mi][nt][1] + b1v) * f0s);
            *(__half2*)&dst[((size_t)bh * SS + s1) * DHD + d] =
                __floats2half2_rn((acc[mi][nt][2] + b0v) * f1s,
                                  (acc[mi][nt][3] + b1v) * f1s);
        }
    }
}

// ---------------------------------------------------------------------------
// Flash attention (exact round-12 config): no online max; QK in fp16
// accumulators; P = ex2.f16x2(score + mask) directly forms PV A-frags;
// row sums via ones-matrix MMA; PV fp32 acc; double-buffered K/V.
// 128 thr (4 warps); block = (bh, 128 q rows); warp owns 32 q rows.
// ---------------------------------------------------------------------------
#define AT_STRIDE 72
__global__ __launch_bounds__(128) void attn_kernel(
    const float* __restrict__ mask,
    float* __restrict__ out)
{
    __shared__ __half Ks[2][64 * AT_STRIDE];
    __shared__ __half Vs[2][64 * AT_STRIDE];
    __shared__ unsigned mkS[2][32];            // half2-packed log2e*mask pairs

    const int bh = blockIdx.y;
    const int b  = bh / HH;
    const int h  = bh % HH;
    const int q0 = blockIdx.x * 128;

    const int tid  = threadIdx.x;
    const int w    = tid >> 5;
    const int lane = tid & 31;
    const int g    = lane >> 2;
    const int tg   = lane & 3;
    const int qw   = w * 32;

    const int rB = (lane & 7) + ((lane & 16) ? 8 : 0);      // QK B (non-trans)
    const int cB = (lane & 8) ? 8 : 0;
    const int rT = (lane & 7) + ((lane & 8) ? 8 : 0);       // PV B (trans)
    const int cT = (lane & 16) ? 8 : 0;

    // Q fragments once from global: 2 m-frags x 4 k-chunks
    unsigned Qa[2][4][4];
    #pragma unroll
    for (int mi = 0; mi < 2; mi++) {
        const size_t qb0 = ((size_t)bh * SS + q0 + qw + mi * 16 + g) * DHD;
        const size_t qb1 = qb0 + 8 * DHD;
        #pragma unroll
        for (int kc = 0; kc < 4; kc++) {
            const int kk = kc * 16;
            Qa[mi][kc][0] = *(const unsigned*)&g_Q[qb0 + kk + 2 * tg];
            Qa[mi][kc][1] = *(const unsigned*)&g_Q[qb1 + kk + 2 * tg];
            Qa[mi][kc][2] = *(const unsigned*)&g_Q[qb0 + kk + 2 * tg + 8];
            Qa[mi][kc][3] = *(const unsigned*)&g_Q[qb1 + kk + 2 * tg + 8];
        }
    }

    {   // prologue: stage tile 0
        #pragma unroll
        for (int i = 0; i < 4; i++) {
            int f = tid + i * 128;
            int r = f >> 3, c8 = (f & 7) * 8;
            cp16(&Ks[0][r * AT_STRIDE + c8], &g_K[((size_t)bh * SS + r) * DHD + c8]);
            cp16(&Vs[0][r * AT_STRIDE + c8], &g_V[((size_t)bh * SS + r) * DHD + c8]);
        }
        CP_COMMIT();
    }
    unsigned mkreg = 0;
    if (tid < 32) {
        float2 mv = *(const float2*)&mask[b * SS + 2 * tid];
        mkreg = h2u(__floats2half2_rn(LOG2E * mv.x, LOG2E * mv.y));
    }

    float o[2][8][4] = {};
    float ol[2][4] = {};                       // ones-MMA row-sum accumulators

    int p = 0;
    for (int kt = 0; kt < 16; kt++) {
        CP_WAIT0();
        if (tid < 32) mkS[p][tid] = mkreg;
        __syncthreads();

        if (kt < 15) {
            const int k0 = (kt + 1) * 64;
            #pragma unroll
            for (int i = 0; i < 4; i++) {
                int f = tid + i * 128;
                int r = f >> 3, c8 = (f & 7) * 8;
                cp16(&Ks[p ^ 1][r * AT_STRIDE + c8],
                     &g_K[((size_t)bh * SS + k0 + r) * DHD + c8]);
                cp16(&Vs[p ^ 1][r * AT_STRIDE + c8],
                     &g_V[((size_t)bh * SS + k0 + r) * DHD + c8]);
            }
            CP_COMMIT();
            if (tid < 32) {
                float2 mv = *(const float2*)&mask[b * SS + k0 + 2 * tid];
                mkreg = h2u(__floats2half2_rn(LOG2E * mv.x, LOG2E * mv.y));
            }
        }

        const __half* Kp = Ks[p];
        const __half* Vp = Vs[p];

        // S' = Q K^T, fp16 accumulators (scores packed half2; K pre-scaled)
        unsigned scH[2][8][2] = {};
        #pragma unroll
        for (int kc = 0; kc < 4; kc++) {
            const int kk = kc * 16;
            #pragma unroll
            for (int ntp = 0; ntp < 4; ntp++) {
                unsigned B[4];
                ldsm4(B, &Kp[(ntp * 16 + rB) * AT_STRIDE + kk + cB]);
                #pragma unroll
                for (int mi = 0; mi < 2; mi++) {
                    mma16h(scH[mi][ntp * 2],     Qa[mi][kc], B[0], B[1]);
                    mma16h(scH[mi][ntp * 2 + 1], Qa[mi][kc], B[2], B[3]);
                }
            }
        }

        // P = exp2(S' + mask'), fully packed (in place -> PV A-fragments)
        #pragma unroll
        for (int mi = 0; mi < 2; mi++) {
            #pragma unroll
            for (int nt = 0; nt < 8; nt++) {
                const unsigned m2 = mkS[p][nt * 4 + tg];
                scH[mi][nt][0] = ex2h2(addh2(scH[mi][nt][0], m2));
                scH[mi][nt][1] = ex2h2(addh2(scH[mi][nt][1], m2));
            }
        }

        // O += P V ; l += P * ones  (both fp32 acc)
        #pragma unroll
        for (int kc = 0; kc < 4; kc++) {
            const int kk = kc * 16;
            unsigned pa[2][4];
            #pragma unroll
            for (int mi = 0; mi < 2; mi++) {
                pa[mi][0] = scH[mi][2 * kc][0];
                pa[mi][1] = scH[mi][2 * kc][1];
                pa[mi][2] = scH[mi][2 * kc + 1][0];
                pa[mi][3] = scH[mi][2 * kc + 1][1];
                mma16(ol[mi], pa[mi], ONES2, ONES2);   // row sums
            }
            #pragma unroll
            for (int ntp = 0; ntp < 4; ntp++) {
                unsigned B[4];
                ldsm4t(B, &Vp[(kk + rT) * AT_STRIDE + ntp * 16 + cT]);
                #pragma unroll
                for (int mi = 0; mi < 2; mi++) {
                    mma16(o[mi][ntp * 2],     pa[mi], B[0], B[1]);
                    mma16(o[mi][ntp * 2 + 1], pa[mi], B[2], B[3]);
                }
            }
        }
        p ^= 1;
    }

    // epilogue: ol[mi][0] = full row sum (row g), ol[mi][2] = row g+8
    #pragma unroll
    for (int mi = 0; mi < 2; mi++) {
        const float inv0 = 1.f / ol[mi][0];
        const float inv1 = 1.f / ol[mi][2];
        const int s0 = q0 + qw + mi * 16 + g;
        const int s1 = s0 + 8;
        #pragma unroll
        for (int nt = 0; nt < 8; nt++) {
            const int d = nt * 8 + 2 * tg;
            *(float2*)(out + ((size_t)(b * SS + s0)) * DD + h * DHD + d) =
                make_float2(o[mi][nt][0] * inv0, o[mi][nt][1] * inv0);
            *(float2*)(out + ((size_t)(b * SS + s1)) * DD + h * DHD + d) =
                make_float2(o[mi][nt][2] * inv1, o[mi][nt][3] * inv1);
        }
    }
}

// ---------------------------------------------------------------------------

extern "C" void kernel_launch(void* const* d_in, const int* in_sizes, int n_in,
                              void* d_out, int out_size)
{
    const float* hidden = (const float*)d_in[0];
    const float* mask   = (const float*)d_in[1];
    const float* click  = (const float*)d_in[2];
    const float* Wq     = (const float*)d_in[3];
    const float* bq     = (const float*)d_in[4];
    const float* Wk     = (const float*)d_in[5];
    const float* bk     = (const float*)d_in[6];
    const float* Wv     = (const float*)d_in[7];
    const float* bv     = (const float*)d_in[8];
    float* out = (float*)d_out;

    convert_kernel<<<NCONV / 256, 256>>>(hidden, Wq, Wk, Wv);

    const int qkv_smem = 4 * 128 * QKV_STRIDE * 2;   // 73728 B
    cudaFuncSetAttribute(qkv_kernel,
                         cudaFuncAttributeMaxDynamicSharedMemorySize, qkv_smem);
    dim3 gA(6, 64, 3);
    qkv_kernel<<<gA, 256, qkv_smem>>>(bq, bk, bv, click);

    dim3 gB(8, 96);
    attn_kernel<<<gB, 128>>>(mask, out);
}